// round 5
// baseline (speedup 1.0000x reference)
#include <cuda_runtime.h>
#include <cuda_bf16.h>

#define DIMV   2048
#define SV     4
#define NTV    5          // S + V
#define NV     2048
#define BV     4
#define TPB    64
#define NWARP  (TPB / 32)
#define CHUNKS (DIMV / (4 * TPB))   // 8 float4 chunks per thread per row
#define QUADS  (DIMV / 4)
#define EPSV   1e-5f

// Scratch (no device allocation allowed).
// g_gp[j][q]: uint4 holding gates t=2j,2j+1 for dim-quad q, bf16-packed.
__device__ uint4 g_gp[3][QUADS];
__device__ float g_gsum[6];        // column sums of the ROUNDED gate values

__global__ void prep_kernel(const float* __restrict__ w,
                            const float* __restrict__ afn,
                            const float* __restrict__ bfn) {
    __shared__ float sred[16][6];
    const int tid = threadIdx.x;          // 512 threads, 1 block; one per dim-quad
    const int d0  = tid * 4;

    float gv[6][4];
#pragma unroll
    for (int i = 0; i < 4; i++) {
        float wv = w[d0 + i];
#pragma unroll
        for (int t = 0; t < NTV; t++)
            gv[t][i] = wv * afn[(d0 + i) * NTV + t];
        gv[5][i] = wv * bfn[d0 + i];
    }

    float part[6];
#pragma unroll
    for (int j = 0; j < 3; j++) {
        const int t0 = 2 * j, t1 = 2 * j + 1;
        __nv_bfloat162 hx = __floats2bfloat162_rn(gv[t0][0], gv[t0][1]);
        __nv_bfloat162 hy = __floats2bfloat162_rn(gv[t0][2], gv[t0][3]);
        __nv_bfloat162 hz = __floats2bfloat162_rn(gv[t1][0], gv[t1][1]);
        __nv_bfloat162 hw = __floats2bfloat162_rn(gv[t1][2], gv[t1][3]);
        uint4 u;
        u.x = *reinterpret_cast<unsigned*>(&hx);
        u.y = *reinterpret_cast<unsigned*>(&hy);
        u.z = *reinterpret_cast<unsigned*>(&hz);
        u.w = *reinterpret_cast<unsigned*>(&hw);
        g_gp[j][tid] = u;
        float2 fx = __bfloat1622float2(hx), fy = __bfloat1622float2(hy);
        float2 fz = __bfloat1622float2(hz), fw = __bfloat1622float2(hw);
        part[t0] = fx.x + fx.y + fy.x + fy.y;
        part[t1] = fz.x + fz.y + fw.x + fw.y;
    }

#pragma unroll
    for (int u = 0; u < 6; u++)
#pragma unroll
        for (int o = 16; o > 0; o >>= 1)
            part[u] += __shfl_xor_sync(0xffffffffu, part[u], o);
    if ((tid & 31) == 0)
#pragma unroll
        for (int u = 0; u < 6; u++) sred[tid >> 5][u] = part[u];
    __syncthreads();
    if (tid < 6) {
        float tot = 0.f;
#pragma unroll
        for (int wp = 0; wp < 16; wp++) tot += sred[wp][tid];
        g_gsum[tid] = tot;
    }
}

__global__ __launch_bounds__(TPB, 12) void hyper_kernel(
    const float* __restrict__ res,
    const float* __restrict__ static_beta,
    const float* __restrict__ static_alpha,
    const float* __restrict__ p_ascale,
    const float* __restrict__ p_bscale,
    float* __restrict__ out)
{
    __shared__ float sred[NWARP][SV * 8];

    const int tid  = threadIdx.x;
    const int warp = tid >> 5;
    const int lane = tid & 31;

    const int token = blockIdx.x;              // 0 .. B*N-1
    const int b = token >> 11;
    const int n = token & (NV - 1);
    const size_t rowstride = (size_t)NV * DIMV;
    const float* base  = res + (size_t)(b * SV) * rowstride + (size_t)n * DIMV;
    float*       obase = out + (size_t)(b * SV) * rowstride + (size_t)n * DIMV;

    // ---- Fused pass A: stream residuals, accumulate sum/ssq + 6 raw gate dots.
    //      acc[u], u = s*8 + f ; f: 0=sum 1=ssq 2..7=dots t0..t5 ----
    float acc[32];
#pragma unroll
    for (int u = 0; u < 32; u++) acc[u] = 0.f;

#pragma unroll 2
    for (int k = 0; k < CHUNKS; k++) {
        const int idx = tid + k * TPB;
        float4 v[SV];
#pragma unroll
        for (int s = 0; s < SV; s++)
            v[s] = __ldg(&((const float4*)(base + (size_t)s * rowstride))[idx]);

#pragma unroll
        for (int s = 0; s < SV; s++) {
            acc[s * 8 + 0] += v[s].x + v[s].y + v[s].z + v[s].w;
            acc[s * 8 + 1] += v[s].x * v[s].x + v[s].y * v[s].y
                            + v[s].z * v[s].z + v[s].w * v[s].w;
        }

#pragma unroll
        for (int j = 0; j < 3; j++) {
            uint4 p = g_gp[j][idx];
            float2 fx = __bfloat1622float2(*reinterpret_cast<__nv_bfloat162*>(&p.x));
            float2 fy = __bfloat1622float2(*reinterpret_cast<__nv_bfloat162*>(&p.y));
            float2 fz = __bfloat1622float2(*reinterpret_cast<__nv_bfloat162*>(&p.z));
            float2 fw = __bfloat1622float2(*reinterpret_cast<__nv_bfloat162*>(&p.w));
#pragma unroll
            for (int s = 0; s < SV; s++) {
                acc[s * 8 + 2 + 2 * j]     += v[s].x * fx.x + v[s].y * fx.y
                                            + v[s].z * fy.x + v[s].w * fy.y;
                acc[s * 8 + 2 + 2 * j + 1] += v[s].x * fz.x + v[s].y * fz.y
                                            + v[s].z * fw.x + v[s].w * fw.y;
            }
        }
    }

    // ---- Butterfly reduction: 32 values across 32 lanes in 31 shuffles.
    //      After stage sequence o=1..16, lane l owns total of value index
    //      vidx(l) = bit-reverse-5(l). ----
    {
        int cnt = 32;
#pragma unroll
        for (int o = 1; o <= 16; o <<= 1) {
            const int h = cnt >> 1;
            const bool up = (lane & o) != 0;
#pragma unroll
            for (int i = 0; i < h; i++) {
                float send = up ? acc[i] : acc[i + h];
                float recv = __shfl_xor_sync(0xffffffffu, send, o);
                float keep = up ? acc[i + h] : acc[i];
                acc[i] = keep + recv;
            }
            cnt = h;
        }
    }
    const int vidx = ((lane & 1) << 4) | ((lane & 2) << 2) | (lane & 4)
                   | ((lane & 8) >> 2) | ((lane & 16) >> 4);
    sred[warp][vidx] = acc[0];
    __syncthreads();   // the ONLY barrier

    // ---- Redundant per-warp finalize: lane u owns value u = s*8+f ----
    float tot = sred[0][lane];
#pragma unroll
    for (int w = 1; w < NWARP; w++) tot += sred[w][lane];

    const int s_own = lane >> 3;
    const int f     = lane & 7;
    const float tsum = __shfl_sync(0xffffffffu, tot, (lane & 24) | 0);
    const float tssq = __shfl_sync(0xffffffffu, tot, (lane & 24) | 1);
    const float mu   = tsum * (1.f / DIMV);
    const float var  = tssq * (1.f / DIMV) - mu * mu;
    const float rsig = rsqrtf(var + EPSV);

    const int j = (f >= 2) ? (f - 2) : 0;      // clamped for safe loads
    const float gs   = g_gsum[j];
    const float dotc = (tot - mu * gs) * rsig;
    const float th   = tanhf(dotc);
    float ab;
    if (f < 7) ab = th * p_ascale[0] + static_alpha[s_own * NTV + j];
    else       ab = th * p_bscale[0] + static_beta[s_own];
    // lanes f=2..6 hold alpha[s][0..4]; lane f=7 holds beta[s]; f<2 garbage.

    // Fold into 4x4 mix matrix on lanes 0..15, then broadcast.
    const int cs = lane >> 2, csp = lane & 3;
    const float beta_s  = __shfl_sync(0xffffffffu, ab, cs * 8 + 7);
    const float alp_sp0 = __shfl_sync(0xffffffffu, ab, csp * 8 + 2);
    const float alp_sps = __shfl_sync(0xffffffffu, ab, csp * 8 + 3 + cs);
    const float Cl = beta_s * alp_sp0 + alp_sps;   // valid on lanes 0..15

    float Cm[SV][SV];
#pragma unroll
    for (int s = 0; s < SV; s++)
#pragma unroll
        for (int sp = 0; sp < SV; sp++)
            Cm[s][sp] = __shfl_sync(0xffffffffu, Cl, s * 4 + sp);

    // ---- Pass C: re-read residuals (L1/L2 hits), 4x4 mix, streaming stores ----
#pragma unroll 2
    for (int k = 0; k < CHUNKS; k++) {
        const int idx = tid + k * TPB;
        float4 v[SV];
#pragma unroll
        for (int s = 0; s < SV; s++)
            v[s] = __ldg(&((const float4*)(base + (size_t)s * rowstride))[idx]);
#pragma unroll
        for (int s = 0; s < SV; s++) {
            float4 o;
            o.x = Cm[s][0] * v[0].x; o.y = Cm[s][0] * v[0].y;
            o.z = Cm[s][0] * v[0].z; o.w = Cm[s][0] * v[0].w;
#pragma unroll
            for (int sp = 1; sp < SV; sp++) {
                o.x += Cm[s][sp] * v[sp].x;
                o.y += Cm[s][sp] * v[sp].y;
                o.z += Cm[s][sp] * v[sp].z;
                o.w += Cm[s][sp] * v[sp].w;
            }
            __stcs(&((float4*)(obase + (size_t)s * rowstride))[idx], o);
        }
    }
}

extern "C" void kernel_launch(void* const* d_in, const int* in_sizes, int n_in,
                              void* d_out, int out_size) {
    const float* res    = (const float*)d_in[0];
    const float* w      = (const float*)d_in[1];
    const float* sbeta  = (const float*)d_in[2];
    const float* salpha = (const float*)d_in[3];
    const float* afn    = (const float*)d_in[4];
    const float* ascale = (const float*)d_in[5];
    const float* bfn    = (const float*)d_in[6];
    const float* bscale = (const float*)d_in[7];
    float* out = (float*)d_out;

    prep_kernel<<<1, 512>>>(w, afn, bfn);
    hyper_kernel<<<BV * NV, TPB>>>(res, sbeta, salpha, ascale, bscale, out);
}

// round 6
// speedup vs baseline: 1.0835x; 1.0835x over previous
#include <cuda_runtime.h>
#include <cuda_bf16.h>

#define DIMV   2048
#define SV     4
#define NTV    5          // S + V
#define NV     2048
#define BV     4
#define TPB    128
#define NWARP  (TPB / 32)
#define CHUNKS (DIMV / (4 * TPB))   // 4 float4 chunks per thread per row
#define QUADS  (DIMV / 4)
#define EPSV   1e-5f

// Scratch (no device allocation allowed).
// g_gp[j][q]: uint4 holding gates t=2j,2j+1 for dim-quad q, bf16-packed.
__device__ uint4 g_gp[3][QUADS];
__device__ float g_gsum[6];        // column sums of the ROUNDED gate values

__global__ void prep_kernel(const float* __restrict__ w,
                            const float* __restrict__ afn,
                            const float* __restrict__ bfn) {
    __shared__ float sred[16][6];
    const int tid = threadIdx.x;          // 512 threads, 1 block; one per dim-quad
    const int d0  = tid * 4;

    float gv[6][4];
#pragma unroll
    for (int i = 0; i < 4; i++) {
        float wv = w[d0 + i];
#pragma unroll
        for (int t = 0; t < NTV; t++)
            gv[t][i] = wv * afn[(d0 + i) * NTV + t];
        gv[5][i] = wv * bfn[d0 + i];
    }

    float part[6];
#pragma unroll
    for (int j = 0; j < 3; j++) {
        const int t0 = 2 * j, t1 = 2 * j + 1;
        __nv_bfloat162 hx = __floats2bfloat162_rn(gv[t0][0], gv[t0][1]);
        __nv_bfloat162 hy = __floats2bfloat162_rn(gv[t0][2], gv[t0][3]);
        __nv_bfloat162 hz = __floats2bfloat162_rn(gv[t1][0], gv[t1][1]);
        __nv_bfloat162 hw = __floats2bfloat162_rn(gv[t1][2], gv[t1][3]);
        uint4 u;
        u.x = *reinterpret_cast<unsigned*>(&hx);
        u.y = *reinterpret_cast<unsigned*>(&hy);
        u.z = *reinterpret_cast<unsigned*>(&hz);
        u.w = *reinterpret_cast<unsigned*>(&hw);
        g_gp[j][tid] = u;
        float2 fx = __bfloat1622float2(hx), fy = __bfloat1622float2(hy);
        float2 fz = __bfloat1622float2(hz), fw = __bfloat1622float2(hw);
        part[t0] = fx.x + fx.y + fy.x + fy.y;
        part[t1] = fz.x + fz.y + fw.x + fw.y;
    }

#pragma unroll
    for (int u = 0; u < 6; u++)
#pragma unroll
        for (int o = 16; o > 0; o >>= 1)
            part[u] += __shfl_xor_sync(0xffffffffu, part[u], o);
    if ((tid & 31) == 0)
#pragma unroll
        for (int u = 0; u < 6; u++) sred[tid >> 5][u] = part[u];
    __syncthreads();
    if (tid < 6) {
        float tot = 0.f;
#pragma unroll
        for (int wp = 0; wp < 16; wp++) tot += sred[wp][tid];
        g_gsum[tid] = tot;
    }
}

__global__ __launch_bounds__(TPB, 6) void hyper_kernel(
    const float* __restrict__ res,
    const float* __restrict__ static_beta,
    const float* __restrict__ static_alpha,
    const float* __restrict__ p_ascale,
    const float* __restrict__ p_bscale,
    float* __restrict__ out)
{
    __shared__ float sred[NWARP][SV * 8];

    const int tid  = threadIdx.x;
    const int warp = tid >> 5;
    const int lane = tid & 31;

    const int token = blockIdx.x;              // 0 .. B*N-1
    const int b = token >> 11;
    const int n = token & (NV - 1);
    const size_t rowstride = (size_t)NV * DIMV;
    const float* base  = res + (size_t)(b * SV) * rowstride + (size_t)n * DIMV;
    float*       obase = out + (size_t)(b * SV) * rowstride + (size_t)n * DIMV;

    // ---- Fused pass A: stream residuals, accumulate sum/ssq + 6 raw gate dots.
    //      acc[u], u = s*8 + f ; f: 0=sum 1=ssq 2..7=dots t0..t5 ----
    float acc[32];
#pragma unroll
    for (int u = 0; u < 32; u++) acc[u] = 0.f;

#pragma unroll
    for (int k = 0; k < CHUNKS; k++) {
        const int idx = tid + k * TPB;
        float4 v[SV];
#pragma unroll
        for (int s = 0; s < SV; s++)
            v[s] = __ldg(&((const float4*)(base + (size_t)s * rowstride))[idx]);

#pragma unroll
        for (int s = 0; s < SV; s++) {
            acc[s * 8 + 0] += v[s].x + v[s].y + v[s].z + v[s].w;
            acc[s * 8 + 1] += v[s].x * v[s].x + v[s].y * v[s].y
                            + v[s].z * v[s].z + v[s].w * v[s].w;
        }

#pragma unroll
        for (int j = 0; j < 3; j++) {
            uint4 p = g_gp[j][idx];
            float2 fx = __bfloat1622float2(*reinterpret_cast<__nv_bfloat162*>(&p.x));
            float2 fy = __bfloat1622float2(*reinterpret_cast<__nv_bfloat162*>(&p.y));
            float2 fz = __bfloat1622float2(*reinterpret_cast<__nv_bfloat162*>(&p.z));
            float2 fw = __bfloat1622float2(*reinterpret_cast<__nv_bfloat162*>(&p.w));
#pragma unroll
            for (int s = 0; s < SV; s++) {
                acc[s * 8 + 2 + 2 * j]     += v[s].x * fx.x + v[s].y * fx.y
                                            + v[s].z * fy.x + v[s].w * fy.y;
                acc[s * 8 + 2 + 2 * j + 1] += v[s].x * fz.x + v[s].y * fz.y
                                            + v[s].z * fw.x + v[s].w * fw.y;
            }
        }
    }

    // ---- Butterfly reduction: 32 values across 32 lanes in 31 shuffles.
    //      After stages o=1..16, lane l owns total of value index
    //      vidx(l) = bit-reverse-5(l). ----
    {
        int cnt = 32;
#pragma unroll
        for (int o = 1; o <= 16; o <<= 1) {
            const int h = cnt >> 1;
            const bool up = (lane & o) != 0;
#pragma unroll
            for (int i = 0; i < h; i++) {
                float send = up ? acc[i] : acc[i + h];
                float recv = __shfl_xor_sync(0xffffffffu, send, o);
                float keep = up ? acc[i + h] : acc[i];
                acc[i] = keep + recv;
            }
            cnt = h;
        }
    }
    const int vidx = ((lane & 1) << 4) | ((lane & 2) << 2) | (lane & 4)
                   | ((lane & 8) >> 2) | ((lane & 16) >> 4);
    sred[warp][vidx] = acc[0];
    __syncthreads();   // the ONLY barrier

    // ---- Redundant per-warp finalize: lane u owns value u = s*8+f ----
    float tot = sred[0][lane];
#pragma unroll
    for (int w = 1; w < NWARP; w++) tot += sred[w][lane];

    const int s_own = lane >> 3;
    const int f     = lane & 7;
    const float tsum = __shfl_sync(0xffffffffu, tot, (lane & 24) | 0);
    const float tssq = __shfl_sync(0xffffffffu, tot, (lane & 24) | 1);
    const float mu   = tsum * (1.f / DIMV);
    const float var  = tssq * (1.f / DIMV) - mu * mu;
    const float rsig = rsqrtf(var + EPSV);

    const int j = (f >= 2) ? (f - 2) : 0;      // clamped for safe loads
    const float gs   = g_gsum[j];
    const float dotc = (tot - mu * gs) * rsig;
    const float th   = tanhf(dotc);
    float ab;
    if (f < 7) ab = th * p_ascale[0] + static_alpha[s_own * NTV + j];
    else       ab = th * p_bscale[0] + static_beta[s_own];
    // lanes f=2..6 hold alpha[s][0..4]; lane f=7 holds beta[s]; f<2 garbage.

    // Fold into 4x4 mix matrix on lanes 0..15, then broadcast.
    const int cs = lane >> 2, csp = lane & 3;
    const float beta_s  = __shfl_sync(0xffffffffu, ab, cs * 8 + 7);
    const float alp_sp0 = __shfl_sync(0xffffffffu, ab, csp * 8 + 2);
    const float alp_sps = __shfl_sync(0xffffffffu, ab, csp * 8 + 3 + cs);
    const float Cl = beta_s * alp_sp0 + alp_sps;   // valid on lanes 0..15

    float Cm[SV][SV];
#pragma unroll
    for (int s = 0; s < SV; s++)
#pragma unroll
        for (int sp = 0; sp < SV; sp++)
            Cm[s][sp] = __shfl_sync(0xffffffffu, Cl, s * 4 + sp);

    // ---- Pass C: re-read residuals (L1 hits at 6 tokens/SM), 4x4 mix,
    //      streaming stores ----
#pragma unroll
    for (int k = 0; k < CHUNKS; k++) {
        const int idx = tid + k * TPB;
        float4 v[SV];
#pragma unroll
        for (int s = 0; s < SV; s++)
            v[s] = __ldg(&((const float4*)(base + (size_t)s * rowstride))[idx]);
#pragma unroll
        for (int s = 0; s < SV; s++) {
            float4 o;
            o.x = Cm[s][0] * v[0].x; o.y = Cm[s][0] * v[0].y;
            o.z = Cm[s][0] * v[0].z; o.w = Cm[s][0] * v[0].w;
#pragma unroll
            for (int sp = 1; sp < SV; sp++) {
                o.x += Cm[s][sp] * v[sp].x;
                o.y += Cm[s][sp] * v[sp].y;
                o.z += Cm[s][sp] * v[sp].z;
                o.w += Cm[s][sp] * v[sp].w;
            }
            __stcs(&((float4*)(obase + (size_t)s * rowstride))[idx], o);
        }
    }
}

extern "C" void kernel_launch(void* const* d_in, const int* in_sizes, int n_in,
                              void* d_out, int out_size) {
    const float* res    = (const float*)d_in[0];
    const float* w      = (const float*)d_in[1];
    const float* sbeta  = (const float*)d_in[2];
    const float* salpha = (const float*)d_in[3];
    const float* afn    = (const float*)d_in[4];
    const float* ascale = (const float*)d_in[5];
    const float* bfn    = (const float*)d_in[6];
    const float* bscale = (const float*)d_in[7];
    float* out = (float*)d_out;

    prep_kernel<<<1, 512>>>(w, afn, bfn);
    hyper_kernel<<<BV * NV, TPB>>>(res, sbeta, salpha, ascale, bscale, out);
}